// round 3
// baseline (speedup 1.0000x reference)
#include <cuda_runtime.h>
#include <cuda_bf16.h>
#include <cstdint>

// Problem constants
#define NN 50000
#define NE 800000
#define F  128

// ---------------- scratch (static device globals; no runtime allocs) --------
__device__ __align__(16) int   g_deg[NN];
__device__ __align__(16) int   g_cursor[NN];
__device__ __align__(16) int   g_rowptr[NN + 1];
__device__ __align__(16) int   g_csrc[NE];
__device__ __align__(16) float g_mean[NN * F];
__device__ __align__(16) float g_h1[NN * F];
__device__ __align__(16) float g_h2[NN * F];
__device__ __align__(16) float g_AB[(size_t)NN * 256];
__device__ int g_is64;

// ---------------- index decode (int32 vs int64 edge_index) -------------------
__global__ void detect_kernel(const void* __restrict__ eidx) {
    // Values are in [0, NN). If stored as int64, the high 32-bit word of each
    // element is 0. If stored as int32, "odd words" are themselves random
    // indices and will not all be zero over 128 samples.
    const int* w = (const int*)eidx;
    int is64 = 1;
    for (int i = 1; i < 256; i += 2)
        if (w[i] != 0) { is64 = 0; break; }
    g_is64 = is64;
}

__device__ __forceinline__ int load_idx(const void* p, long long pos) {
    int v;
    if (g_is64) v = (int)((const long long*)p)[pos];
    else        v = ((const int*)p)[pos];
    // clamp for safety (never trap)
    return min(max(v, 0), NN - 1);
}
// src index of edge e: pos = e ; dst index of edge e: pos = NE + e

// ---------------- CSR build --------------------------------------------------
__global__ void zero_kernel() {
    int i = blockIdx.x * blockDim.x + threadIdx.x;
    if (i < NN) { g_deg[i] = 0; g_cursor[i] = 0; }
}

__global__ void hist_kernel(const void* __restrict__ eidx) {
    int e = blockIdx.x * blockDim.x + threadIdx.x;
    if (e < NE) atomicAdd(&g_deg[load_idx(eidx, (long long)NE + e)], 1);
}

// single-block exclusive scan over g_deg -> g_rowptr
__global__ void scan_kernel() {
    __shared__ int sums[1024];
    const int CH = (NN + 1023) / 1024;  // 49
    int t = threadIdx.x;
    int start = t * CH;
    int end   = min(start + CH, NN);
    int s = 0;
    for (int i = start; i < end; i++) s += g_deg[i];
    sums[t] = s;
    __syncthreads();
    for (int off = 1; off < 1024; off <<= 1) {
        int v = 0;
        if (t >= off) v = sums[t - off];
        __syncthreads();
        if (t >= off) sums[t] += v;
        __syncthreads();
    }
    int run = (t == 0) ? 0 : sums[t - 1];
    for (int i = start; i < end; i++) {
        g_rowptr[i] = run;
        run += g_deg[i];
    }
    if (t == 0) g_rowptr[NN] = NE;
}

__global__ void scatter_kernel(const void* __restrict__ eidx) {
    int e = blockIdx.x * blockDim.x + threadIdx.x;
    if (e < NE) {
        int d = load_idx(eidx, (long long)NE + e);
        int pos = g_rowptr[d] + atomicAdd(&g_cursor[d], 1);
        if (pos >= 0 && pos < NE) g_csrc[pos] = load_idx(eidx, e);
    }
}

// ---------------- segment mean: warp per node --------------------------------
// xin == nullptr -> aggregate g_h1 instead
__global__ void aggregate_kernel(const float* __restrict__ xin) {
    const float* __restrict__ p = xin ? xin : (const float*)g_h1;
    int gw   = (blockIdx.x * blockDim.x + threadIdx.x) >> 5;
    int lane = threadIdx.x & 31;
    if (gw >= NN) return;
    int r0 = g_rowptr[gw];
    int r1 = g_rowptr[gw + 1];
    float4 acc = make_float4(0.f, 0.f, 0.f, 0.f);
    for (int i = r0; i < r1; i++) {
        int s = g_csrc[i];
        float4 v = *(const float4*)(p + (size_t)s * F + lane * 4);
        acc.x += v.x; acc.y += v.y; acc.z += v.z; acc.w += v.w;
    }
    float inv = 1.0f / (float)max(r1 - r0, 1);
    acc.x *= inv; acc.y *= inv; acc.z *= inv; acc.w *= inv;
    *(float4*)(g_mean + (size_t)gw * F + lane * 4) = acc;
}

// ---------------- fp32 GEMM: C[M,128] = A1@B1 (+ A2@B2) (+bias) (relu?) ------
// MODE 0: C=g_h1 = relu( g_mean@B1 + Aext@B2 + bias ), ldc=128, K=256
// MODE 1: C=g_h2 =       g_mean@B1 + g_h1@B2 + bias  , ldc=128, K=256
// MODE 2: C=g_AB[:,0:128]   = g_h2@B1, ldc=256, K=128
// MODE 3: C=g_AB[:,128:256] = g_h2@B1, ldc=256, K=128
#define BM 128
#define BN 128
#define BK 8

template <int MODE>
__global__ __launch_bounds__(256)
void gemm128(const float* __restrict__ Aext,
             const float* __restrict__ B1, const float* __restrict__ B2,
             const float* __restrict__ bias, int M)
{
    constexpr int  Ktot = (MODE <= 1) ? 256 : 128;
    constexpr bool RELU = (MODE == 0);
    constexpr bool BIAS = (MODE <= 1);
    const int ldc = (MODE >= 2) ? 256 : 128;

    const float* A1 = (MODE <= 1) ? (const float*)g_mean : (const float*)g_h2;
    const float* A2 = (MODE == 0) ? Aext
                    : (MODE == 1) ? (const float*)g_h1 : nullptr;
    float* C = (MODE == 0) ? (float*)g_h1
             : (MODE == 1) ? (float*)g_h2
             : (MODE == 2) ? (float*)g_AB
             :               (float*)g_AB + 128;

    __shared__ float As[BK][BM];
    __shared__ float Bs[BK][BN];

    int tid = threadIdx.x;
    int m0  = blockIdx.x * BM;
    int tx  = tid & 15;   // 0..15 (N dim)
    int ty  = tid >> 4;   // 0..15 (M dim)

    float acc[8][8];
#pragma unroll
    for (int i = 0; i < 8; i++)
#pragma unroll
        for (int j = 0; j < 8; j++) acc[i][j] = 0.f;

    const int ar  = tid >> 1;          // 0..127
    const int ac4 = (tid & 1) * 4;     // 0 or 4
    const int br  = tid >> 5;          // 0..7
    const int bc4 = (tid & 31) * 4;    // 0..124

    for (int kc = 0; kc < Ktot; kc += BK) {
        const float* Ap;
        const float* Bp;
        int kk0;
        if (kc < 128) { Ap = A1; Bp = B1; kk0 = kc; }
        else          { Ap = A2; Bp = B2; kk0 = kc - 128; }

        {
            int gm = m0 + ar;
            float4 v = make_float4(0.f, 0.f, 0.f, 0.f);
            if (gm < M) v = *(const float4*)(Ap + (size_t)gm * 128 + kk0 + ac4);
            As[ac4 + 0][ar] = v.x;
            As[ac4 + 1][ar] = v.y;
            As[ac4 + 2][ar] = v.z;
            As[ac4 + 3][ar] = v.w;
        }
        {
            float4 v = *(const float4*)(Bp + (size_t)(kk0 + br) * 128 + bc4);
            *(float4*)&Bs[br][bc4] = v;
        }
        __syncthreads();

#pragma unroll
        for (int kk = 0; kk < BK; kk++) {
            float a[8], b[8];
            *(float4*)&a[0] = *(float4*)&As[kk][ty * 4];
            *(float4*)&a[4] = *(float4*)&As[kk][64 + ty * 4];
            *(float4*)&b[0] = *(float4*)&Bs[kk][tx * 4];
            *(float4*)&b[4] = *(float4*)&Bs[kk][64 + tx * 4];
#pragma unroll
            for (int i = 0; i < 8; i++)
#pragma unroll
                for (int j = 0; j < 8; j++)
                    acc[i][j] = fmaf(a[i], b[j], acc[i][j]);
        }
        __syncthreads();
    }

#pragma unroll
    for (int i = 0; i < 8; i++) {
        int r  = (i < 4) ? (ty * 4 + i) : (64 + ty * 4 + (i - 4));
        int gm = m0 + r;
        if (gm >= M) continue;
#pragma unroll
        for (int jh = 0; jh < 2; jh++) {
            int c = jh ? (64 + tx * 4) : (tx * 4);
            float4 v;
            v.x = acc[i][jh * 4 + 0];
            v.y = acc[i][jh * 4 + 1];
            v.z = acc[i][jh * 4 + 2];
            v.w = acc[i][jh * 4 + 3];
            if (BIAS) {
                v.x += bias[c + 0]; v.y += bias[c + 1];
                v.z += bias[c + 2]; v.w += bias[c + 3];
            }
            if (RELU) {
                v.x = fmaxf(v.x, 0.f); v.y = fmaxf(v.y, 0.f);
                v.z = fmaxf(v.z, 0.f); v.w = fmaxf(v.w, 0.f);
            }
            *(float4*)(C + (size_t)gm * ldc + c) = v;
        }
    }
}

// ---------------- edge classifier: warp per edge ------------------------------
__global__ __launch_bounds__(256)
void edge_kernel(const void* __restrict__ eidx,
                 const float* __restrict__ ea,
                 const float* __restrict__ Wc1,
                 const float* __restrict__ bc1,
                 const float* __restrict__ Wc2,
                 const float* __restrict__ bc2,
                 float* __restrict__ out)
{
    __shared__ float sWe0[128], sWe1[128], sWe2[128], sb[128], sw2[128];
    int tid = threadIdx.x;
    if (tid < 128) {
        sWe0[tid] = Wc1[256 * 128 + tid];
        sWe1[tid] = Wc1[257 * 128 + tid];
        sWe2[tid] = Wc1[258 * 128 + tid];
        sb[tid]   = bc1[tid];
        sw2[tid]  = Wc2[tid];
    }
    __syncthreads();

    int e = blockIdx.x * (blockDim.x >> 5) + (tid >> 5);
    if (e >= NE) return;
    int lane = tid & 31;
    int j = lane * 4;

    int s = load_idx(eidx, e);
    int d = load_idx(eidx, (long long)NE + e);
    float4 a  = *(const float4*)(g_AB + (size_t)s * 256 + j);
    float4 b  = *(const float4*)(g_AB + (size_t)d * 256 + 128 + j);
    float4 w0 = *(const float4*)&sWe0[j];
    float4 w1 = *(const float4*)&sWe1[j];
    float4 w2 = *(const float4*)&sWe2[j];
    float4 bb = *(const float4*)&sb[j];
    float4 wc = *(const float4*)&sw2[j];

    float e0 = ea[(size_t)e * 3 + 0];
    float e1 = ea[(size_t)e * 3 + 1];
    float e2 = ea[(size_t)e * 3 + 2];

    float h, acc = 0.f;
    h = a.x + b.x + e0 * w0.x + e1 * w1.x + e2 * w2.x + bb.x;
    acc += fmaxf(h, 0.f) * wc.x;
    h = a.y + b.y + e0 * w0.y + e1 * w1.y + e2 * w2.y + bb.y;
    acc += fmaxf(h, 0.f) * wc.y;
    h = a.z + b.z + e0 * w0.z + e1 * w1.z + e2 * w2.z + bb.z;
    acc += fmaxf(h, 0.f) * wc.z;
    h = a.w + b.w + e0 * w0.w + e1 * w1.w + e2 * w2.w + bb.w;
    acc += fmaxf(h, 0.f) * wc.w;

#pragma unroll
    for (int off = 16; off > 0; off >>= 1)
        acc += __shfl_xor_sync(0xFFFFFFFFu, acc, off);

    if (lane == 0) out[e] = acc + bc2[0];
}

// ---------------- launch ------------------------------------------------------
extern "C" void kernel_launch(void* const* d_in, const int* in_sizes, int n_in,
                              void* d_out, int out_size)
{
    const float* x    = (const float*)d_in[0];
    const void*  eidx = d_in[1];
    const float* ea   = (const float*)d_in[2];
    const float* W1l  = (const float*)d_in[3];
    const float* b1l  = (const float*)d_in[4];
    const float* W1r  = (const float*)d_in[5];
    const float* W2l  = (const float*)d_in[6];
    const float* b2l  = (const float*)d_in[7];
    const float* W2r  = (const float*)d_in[8];
    const float* Wc1  = (const float*)d_in[9];
    const float* bc1  = (const float*)d_in[10];
    const float* Wc2  = (const float*)d_in[11];
    const float* bc2  = (const float*)d_in[12];
    float* out = (float*)d_out;

    // 0) detect edge_index dtype (int32 vs int64)
    detect_kernel<<<1, 1>>>(eidx);

    // 1) CSR build (by dst)
    zero_kernel<<<(NN + 255) / 256, 256>>>();
    hist_kernel<<<(NE + 255) / 256, 256>>>(eidx);
    scan_kernel<<<1, 1024>>>();
    scatter_kernel<<<(NE + 255) / 256, 256>>>(eidx);

    const int aggGrid  = (NN * 32 + 255) / 256;
    const int gemmGrid = (NN + BM - 1) / BM;  // 391

    // 2) conv1: h1 = relu(mean(x) @ W1l + b1l + x @ W1r)
    aggregate_kernel<<<aggGrid, 256>>>(x);
    gemm128<0><<<gemmGrid, 256>>>(x, W1l, W1r, b1l, NN);

    // 3) conv2: h2 = mean(h1) @ W2l + b2l + h1 @ W2r
    aggregate_kernel<<<aggGrid, 256>>>(nullptr);
    gemm128<1><<<gemmGrid, 256>>>(nullptr, W2l, W2r, b2l, NN);

    // 4) per-node edge-MLP pre-projection: A = h2@Wc1[:128,:], B = h2@Wc1[128:256,:]
    gemm128<2><<<gemmGrid, 256>>>(nullptr, Wc1,             nullptr, nullptr, NN);
    gemm128<3><<<gemmGrid, 256>>>(nullptr, Wc1 + 128 * 128, nullptr, nullptr, NN);

    // 5) edge classifier: warp per edge
    edge_kernel<<<(NE * 32 + 255) / 256, 256>>>(eidx, ea, Wc1, bc1, Wc2, bc2, out);
}

// round 4
// speedup vs baseline: 1.1673x; 1.1673x over previous
#include <cuda_runtime.h>
#include <cuda_fp16.h>
#include <cuda_bf16.h>
#include <cstdint>

// Problem constants
#define NN 50000
#define NE 800000
#define F  128

// ---------------- scratch (static device globals; no runtime allocs) --------
__device__ __align__(16) int    g_deg[NN];
__device__ __align__(16) int    g_cursor[NN];
__device__ __align__(16) int    g_rowptr[NN + 1];
__device__ __align__(16) int    g_csrc[NE];
__device__ __align__(16) float  g_mean[NN * F];
__device__ __align__(16) float  g_h1[NN * F];
__device__ __align__(16) float  g_h2[NN * F];
__device__ __align__(16) __half g_ABh[(size_t)NN * 256];
__device__ __align__(16) int    g_bsum[64];
__device__ __align__(16) int    g_boff[64];
__device__ int g_is64;

// ---------------- index decode (int32 vs int64 edge_index) -------------------
__global__ void detect_kernel(const void* __restrict__ eidx) {
    const int* w = (const int*)eidx;
    int is64 = 1;
    for (int i = 1; i < 256; i += 2)
        if (w[i] != 0) { is64 = 0; break; }
    g_is64 = is64;
}

__device__ __forceinline__ int load_idx(const void* p, long long pos) {
    int v;
    if (g_is64) v = (int)((const long long*)p)[pos];
    else        v = ((const int*)p)[pos];
    return min(max(v, 0), NN - 1);
}

// ---------------- CSR build --------------------------------------------------
__global__ void zero_kernel() {
    int i = blockIdx.x * blockDim.x + threadIdx.x;
    if (i < NN) { g_deg[i] = 0; g_cursor[i] = 0; }
}

__global__ void hist_kernel(const void* __restrict__ eidx) {
    int e = blockIdx.x * blockDim.x + threadIdx.x;
    if (e < NE) atomicAdd(&g_deg[load_idx(eidx, (long long)NE + e)], 1);
}

// ---- hierarchical scan: phase A (49 blocks x 1024: per-block exclusive scan)
__global__ void scanA_kernel() {
    __shared__ int warp_sums[32];
    int b = blockIdx.x, t = threadIdx.x;
    int i = b * 1024 + t;
    int lane = t & 31, w = t >> 5;
    int v = (i < NN) ? g_deg[i] : 0;
    // warp inclusive scan
    int s = v;
#pragma unroll
    for (int off = 1; off < 32; off <<= 1) {
        int n = __shfl_up_sync(0xFFFFFFFFu, s, off);
        if (lane >= off) s += n;
    }
    if (lane == 31) warp_sums[w] = s;
    __syncthreads();
    if (w == 0) {
        int ws = warp_sums[lane];
#pragma unroll
        for (int off = 1; off < 32; off <<= 1) {
            int n = __shfl_up_sync(0xFFFFFFFFu, ws, off);
            if (lane >= off) ws += n;
        }
        warp_sums[lane] = ws;
    }
    __syncthreads();
    int woff = (w == 0) ? 0 : warp_sums[w - 1];
    int incl = s + woff;
    if (i < NN) g_rowptr[i] = incl - v;       // exclusive within block
    if (t == 1023) g_bsum[b] = incl;          // block total
}

// ---- phase B: 1 block of 64 threads scans the 49 block sums (exclusive)
__global__ void scanB_kernel(int nblocks) {
    __shared__ int sh[64];
    int t = threadIdx.x;
    int v = (t < nblocks) ? g_bsum[t] : 0;
    sh[t] = v;
    __syncthreads();
    for (int off = 1; off < 64; off <<= 1) {
        int n = (t >= off) ? sh[t - off] : 0;
        __syncthreads();
        sh[t] += n;
        __syncthreads();
    }
    g_boff[t] = sh[t] - v;
    if (t == 0) g_rowptr[NN] = NE;
}

// ---- phase C: add block offsets
__global__ void scanC_kernel() {
    int i = blockIdx.x * 1024 + threadIdx.x;
    if (i < NN) g_rowptr[i] += g_boff[blockIdx.x];
}

__global__ void scatter_kernel(const void* __restrict__ eidx) {
    int e = blockIdx.x * blockDim.x + threadIdx.x;
    if (e < NE) {
        int d = load_idx(eidx, (long long)NE + e);
        int pos = g_rowptr[d] + atomicAdd(&g_cursor[d], 1);
        if (pos >= 0 && pos < NE) g_csrc[pos] = load_idx(eidx, e);
    }
}

// ---------------- segment mean: warp per node --------------------------------
__global__ void aggregate_kernel(const float* __restrict__ xin) {
    const float* __restrict__ p = xin ? xin : (const float*)g_h1;
    int gw   = (blockIdx.x * blockDim.x + threadIdx.x) >> 5;
    int lane = threadIdx.x & 31;
    if (gw >= NN) return;
    int r0 = g_rowptr[gw];
    int r1 = g_rowptr[gw + 1];
    float4 acc = make_float4(0.f, 0.f, 0.f, 0.f);
    for (int i = r0; i < r1; i++) {
        int s = g_csrc[i];
        float4 v = *(const float4*)(p + (size_t)s * F + lane * 4);
        acc.x += v.x; acc.y += v.y; acc.z += v.z; acc.w += v.w;
    }
    float inv = 1.0f / (float)max(r1 - r0, 1);
    acc.x *= inv; acc.y *= inv; acc.z *= inv; acc.w *= inv;
    *(float4*)(g_mean + (size_t)gw * F + lane * 4) = acc;
}

// ---------------- fp32 GEMM with double-buffered smem pipeline ---------------
// MODE 0: g_h1 = relu( g_mean@B1 + Aext@B2 + bias ), fp32 out, ldc=128, K=256
// MODE 1: g_h2 =       g_mean@B1 + g_h1@B2 + bias  , fp32 out, ldc=128, K=256
// MODE 2: g_ABh[:,0:128]   = h2@B1 (fp16 out), ldc=256, K=128
// MODE 3: g_ABh[:,128:256] = h2@B1 (fp16 out), ldc=256, K=128
#define BM 128
#define BN 128
#define BK 8

template <int MODE>
__global__ __launch_bounds__(256)
void gemm128(const float* __restrict__ Aext,
             const float* __restrict__ B1, const float* __restrict__ B2,
             const float* __restrict__ bias, int M)
{
    constexpr int  Ktot   = (MODE <= 1) ? 256 : 128;
    constexpr int  NCHUNK = Ktot / BK;
    constexpr bool RELU   = (MODE == 0);
    constexpr bool BIAS   = (MODE <= 1);

    const float* A1 = (MODE <= 1) ? (const float*)g_mean : (const float*)g_h2;
    const float* A2 = (MODE == 0) ? Aext
                    : (MODE == 1) ? (const float*)g_h1 : nullptr;

    __shared__ float As[2][BK][BM];
    __shared__ float Bs[2][BK][BN];

    int tid = threadIdx.x;
    int m0  = blockIdx.x * BM;
    int tx  = tid & 15;
    int ty  = tid >> 4;

    float acc[8][8];
#pragma unroll
    for (int i = 0; i < 8; i++)
#pragma unroll
        for (int j = 0; j < 8; j++) acc[i][j] = 0.f;

    const int ar  = tid >> 1;
    const int ac4 = (tid & 1) * 4;
    const int br  = tid >> 5;
    const int bc4 = (tid & 31) * 4;
    const int gm_a = m0 + ar;

    float4 va, vb;
    auto load_chunk = [&](int ch) {
        int kc = ch * BK;
        const float* Ap; const float* Bp; int kk0;
        if (kc < 128) { Ap = A1; Bp = B1; kk0 = kc; }
        else          { Ap = A2; Bp = B2; kk0 = kc - 128; }
        va = make_float4(0.f, 0.f, 0.f, 0.f);
        if (gm_a < M) va = *(const float4*)(Ap + (size_t)gm_a * 128 + kk0 + ac4);
        vb = *(const float4*)(Bp + (size_t)(kk0 + br) * 128 + bc4);
    };
    auto store_chunk = [&](int buf) {
        As[buf][ac4 + 0][ar] = va.x;
        As[buf][ac4 + 1][ar] = va.y;
        As[buf][ac4 + 2][ar] = va.z;
        As[buf][ac4 + 3][ar] = va.w;
        *(float4*)&Bs[buf][br][bc4] = vb;
    };

    load_chunk(0);
    store_chunk(0);
    __syncthreads();

    for (int ch = 0; ch < NCHUNK; ch++) {
        int cur = ch & 1;
        if (ch + 1 < NCHUNK) load_chunk(ch + 1);

#pragma unroll
        for (int kk = 0; kk < BK; kk++) {
            float a[8], b[8];
            *(float4*)&a[0] = *(float4*)&As[cur][kk][ty * 4];
            *(float4*)&a[4] = *(float4*)&As[cur][kk][64 + ty * 4];
            *(float4*)&b[0] = *(float4*)&Bs[cur][kk][tx * 4];
            *(float4*)&b[4] = *(float4*)&Bs[cur][kk][64 + tx * 4];
#pragma unroll
            for (int i = 0; i < 8; i++)
#pragma unroll
                for (int j = 0; j < 8; j++)
                    acc[i][j] = fmaf(a[i], b[j], acc[i][j]);
        }

        if (ch + 1 < NCHUNK) {
            store_chunk(cur ^ 1);
            __syncthreads();
        }
    }

    // epilogue
#pragma unroll
    for (int i = 0; i < 8; i++) {
        int r  = (i < 4) ? (ty * 4 + i) : (64 + ty * 4 + (i - 4));
        int gm = m0 + r;
        if (gm >= M) continue;
#pragma unroll
        for (int jh = 0; jh < 2; jh++) {
            int c = jh ? (64 + tx * 4) : (tx * 4);
            float4 v;
            v.x = acc[i][jh * 4 + 0];
            v.y = acc[i][jh * 4 + 1];
            v.z = acc[i][jh * 4 + 2];
            v.w = acc[i][jh * 4 + 3];
            if (BIAS) {
                v.x += bias[c + 0]; v.y += bias[c + 1];
                v.z += bias[c + 2]; v.w += bias[c + 3];
            }
            if (RELU) {
                v.x = fmaxf(v.x, 0.f); v.y = fmaxf(v.y, 0.f);
                v.z = fmaxf(v.z, 0.f); v.w = fmaxf(v.w, 0.f);
            }
            if (MODE <= 1) {
                float* C = (MODE == 0) ? (float*)g_h1 : (float*)g_h2;
                *(float4*)(C + (size_t)gm * 128 + c) = v;
            } else {
                __half* C = (MODE == 2) ? (__half*)g_ABh : (__half*)g_ABh + 128;
                __half2 h01 = __floats2half2_rn(v.x, v.y);
                __half2 h23 = __floats2half2_rn(v.z, v.w);
                uint2 pack;
                pack.x = *(unsigned*)&h01;
                pack.y = *(unsigned*)&h23;
                *(uint2*)(C + (size_t)gm * 256 + c) = pack;
            }
        }
    }
}

// ---------------- edge classifier: warp per edge (fp16 AB table) -------------
__global__ __launch_bounds__(256)
void edge_kernel(const void* __restrict__ eidx,
                 const float* __restrict__ ea,
                 const float* __restrict__ Wc1,
                 const float* __restrict__ bc1,
                 const float* __restrict__ Wc2,
                 const float* __restrict__ bc2,
                 float* __restrict__ out)
{
    __shared__ float sWe0[128], sWe1[128], sWe2[128], sb[128], sw2[128];
    int tid = threadIdx.x;
    if (tid < 128) {
        sWe0[tid] = Wc1[256 * 128 + tid];
        sWe1[tid] = Wc1[257 * 128 + tid];
        sWe2[tid] = Wc1[258 * 128 + tid];
        sb[tid]   = bc1[tid];
        sw2[tid]  = Wc2[tid];
    }
    __syncthreads();

    int e = blockIdx.x * (blockDim.x >> 5) + (tid >> 5);
    if (e >= NE) return;
    int lane = tid & 31;
    int j = lane * 4;

    int s = load_idx(eidx, e);
    int d = load_idx(eidx, (long long)NE + e);

    uint2 av = *(const uint2*)(g_ABh + (size_t)s * 256 + j);
    uint2 bv = *(const uint2*)(g_ABh + (size_t)d * 256 + 128 + j);
    float2 a01 = __half22float2(*(__half2*)&av.x);
    float2 a23 = __half22float2(*(__half2*)&av.y);
    float2 b01 = __half22float2(*(__half2*)&bv.x);
    float2 b23 = __half22float2(*(__half2*)&bv.y);

    float4 w0 = *(const float4*)&sWe0[j];
    float4 w1 = *(const float4*)&sWe1[j];
    float4 w2 = *(const float4*)&sWe2[j];
    float4 bb = *(const float4*)&sb[j];
    float4 wc = *(const float4*)&sw2[j];

    float e0 = ea[(size_t)e * 3 + 0];
    float e1 = ea[(size_t)e * 3 + 1];
    float e2 = ea[(size_t)e * 3 + 2];

    float h, acc = 0.f;
    h = a01.x + b01.x + e0 * w0.x + e1 * w1.x + e2 * w2.x + bb.x;
    acc += fmaxf(h, 0.f) * wc.x;
    h = a01.y + b01.y + e0 * w0.y + e1 * w1.y + e2 * w2.y + bb.y;
    acc += fmaxf(h, 0.f) * wc.y;
    h = a23.x + b23.x + e0 * w0.z + e1 * w1.z + e2 * w2.z + bb.z;
    acc += fmaxf(h, 0.f) * wc.z;
    h = a23.y + b23.y + e0 * w0.w + e1 * w1.w + e2 * w2.w + bb.w;
    acc += fmaxf(h, 0.f) * wc.w;

#pragma unroll
    for (int off = 16; off > 0; off >>= 1)
        acc += __shfl_xor_sync(0xFFFFFFFFu, acc, off);

    if (lane == 0) out[e] = acc + bc2[0];
}

// ---------------- launch ------------------------------------------------------
extern "C" void kernel_launch(void* const* d_in, const int* in_sizes, int n_in,
                              void* d_out, int out_size)
{
    const float* x    = (const float*)d_in[0];
    const void*  eidx = d_in[1];
    const float* ea   = (const float*)d_in[2];
    const float* W1l  = (const float*)d_in[3];
    const float* b1l  = (const float*)d_in[4];
    const float* W1r  = (const float*)d_in[5];
    const float* W2l  = (const float*)d_in[6];
    const float* b2l  = (const float*)d_in[7];
    const float* W2r  = (const float*)d_in[8];
    const float* Wc1  = (const float*)d_in[9];
    const float* bc1  = (const float*)d_in[10];
    const float* Wc2  = (const float*)d_in[11];
    const float* bc2  = (const float*)d_in[12];
    float* out = (float*)d_out;

    const int SCAN_BLOCKS = (NN + 1023) / 1024;  // 49

    // 0) detect edge_index dtype
    detect_kernel<<<1, 1>>>(eidx);

    // 1) CSR build (by dst)
    zero_kernel<<<(NN + 255) / 256, 256>>>();
    hist_kernel<<<(NE + 255) / 256, 256>>>(eidx);
    scanA_kernel<<<SCAN_BLOCKS, 1024>>>();
    scanB_kernel<<<1, 64>>>(SCAN_BLOCKS);
    scanC_kernel<<<SCAN_BLOCKS, 1024>>>();
    scatter_kernel<<<(NE + 255) / 256, 256>>>(eidx);

    const int aggGrid  = (NN * 32 + 255) / 256;
    const int gemmGrid = (NN + BM - 1) / BM;  // 391

    // 2) conv1: h1 = relu(mean(x) @ W1l + b1l + x @ W1r)
    aggregate_kernel<<<aggGrid, 256>>>(x);
    gemm128<0><<<gemmGrid, 256>>>(x, W1l, W1r, b1l, NN);

    // 3) conv2: h2 = mean(h1) @ W2l + b2l + h1 @ W2r
    aggregate_kernel<<<aggGrid, 256>>>(nullptr);
    gemm128<1><<<gemmGrid, 256>>>(nullptr, W2l, W2r, b2l, NN);

    // 4) per-node edge-MLP pre-projection (fp16 out)
    gemm128<2><<<gemmGrid, 256>>>(nullptr, Wc1,             nullptr, nullptr, NN);
    gemm128<3><<<gemmGrid, 256>>>(nullptr, Wc1 + 128 * 128, nullptr, nullptr, NN);

    // 5) edge classifier
    edge_kernel<<<(NE * 32 + 255) / 256, 256>>>(eidx, ea, Wc1, bc1, Wc2, bc2, out);
}

// round 5
// speedup vs baseline: 1.3245x; 1.1346x over previous
#include <cuda_runtime.h>
#include <cuda_fp16.h>
#include <cuda_bf16.h>
#include <cstdint>

// Problem constants
#define NN 50000
#define NE 800000
#define F  128

// ---------------- scratch (static device globals; no runtime allocs) --------
__device__ __align__(16) int    g_deg[NN];
__device__ __align__(16) int    g_cursor[NN];
__device__ __align__(16) int    g_rowptr[NN + 1];
__device__ __align__(16) int    g_csrc[NE];
__device__ __align__(16) float  g_mean[NN * F];
__device__ __align__(16) float  g_h1[NN * F];
__device__ __align__(16) float  g_h2[NN * F];
__device__ __align__(16) __half g_ABh[(size_t)NN * 256];
__device__ __align__(16) int    g_bsum[64];
__device__ __align__(16) int    g_boff[64];
__device__ int g_is64;

// ---------------- packed fp32x2 helpers (Blackwell FFMA2) --------------------
__device__ __forceinline__ unsigned long long pack2(float x, float y) {
    unsigned long long r;
    asm("mov.b64 %0, {%1, %2};" : "=l"(r) : "f"(x), "f"(y));
    return r;
}
__device__ __forceinline__ void unpack2(unsigned long long v, float& x, float& y) {
    asm("mov.b64 {%0, %1}, %2;" : "=f"(x), "=f"(y) : "l"(v));
}
__device__ __forceinline__ void ffma2(unsigned long long& d,
                                      unsigned long long a,
                                      unsigned long long b) {
    asm("fma.rn.f32x2 %0, %1, %2, %0;" : "+l"(d) : "l"(a), "l"(b));
}

// ---------------- index decode (int32 vs int64 edge_index) -------------------
__global__ void detect_kernel(const void* __restrict__ eidx) {
    const int* w = (const int*)eidx;
    int is64 = 1;
    for (int i = 1; i < 256; i += 2)
        if (w[i] != 0) { is64 = 0; break; }
    g_is64 = is64;
}

__device__ __forceinline__ int load_idx(const void* p, long long pos) {
    int v;
    if (g_is64) v = (int)((const long long*)p)[pos];
    else        v = ((const int*)p)[pos];
    return min(max(v, 0), NN - 1);
}

// ---------------- CSR build --------------------------------------------------
__global__ void zero_kernel() {
    int i = blockIdx.x * blockDim.x + threadIdx.x;
    if (i < NN) { g_deg[i] = 0; g_cursor[i] = 0; }
}

__global__ void hist_kernel(const void* __restrict__ eidx) {
    int e = blockIdx.x * blockDim.x + threadIdx.x;
    if (e < NE) atomicAdd(&g_deg[load_idx(eidx, (long long)NE + e)], 1);
}

__global__ void scanA_kernel() {
    __shared__ int warp_sums[32];
    int b = blockIdx.x, t = threadIdx.x;
    int i = b * 1024 + t;
    int lane = t & 31, w = t >> 5;
    int v = (i < NN) ? g_deg[i] : 0;
    int s = v;
#pragma unroll
    for (int off = 1; off < 32; off <<= 1) {
        int n = __shfl_up_sync(0xFFFFFFFFu, s, off);
        if (lane >= off) s += n;
    }
    if (lane == 31) warp_sums[w] = s;
    __syncthreads();
    if (w == 0) {
        int ws = warp_sums[lane];
#pragma unroll
        for (int off = 1; off < 32; off <<= 1) {
            int n = __shfl_up_sync(0xFFFFFFFFu, ws, off);
            if (lane >= off) ws += n;
        }
        warp_sums[lane] = ws;
    }
    __syncthreads();
    int woff = (w == 0) ? 0 : warp_sums[w - 1];
    int incl = s + woff;
    if (i < NN) g_rowptr[i] = incl - v;
    if (t == 1023) g_bsum[b] = incl;
}

__global__ void scanB_kernel(int nblocks) {
    __shared__ int sh[64];
    int t = threadIdx.x;
    int v = (t < nblocks) ? g_bsum[t] : 0;
    sh[t] = v;
    __syncthreads();
    for (int off = 1; off < 64; off <<= 1) {
        int n = (t >= off) ? sh[t - off] : 0;
        __syncthreads();
        sh[t] += n;
        __syncthreads();
    }
    g_boff[t] = sh[t] - v;
    if (t == 0) g_rowptr[NN] = NE;
}

__global__ void scanC_kernel() {
    int i = blockIdx.x * 1024 + threadIdx.x;
    if (i < NN) g_rowptr[i] += g_boff[blockIdx.x];
}

__global__ void scatter_kernel(const void* __restrict__ eidx) {
    int e = blockIdx.x * blockDim.x + threadIdx.x;
    if (e < NE) {
        int d = load_idx(eidx, (long long)NE + e);
        int pos = g_rowptr[d] + atomicAdd(&g_cursor[d], 1);
        if (pos >= 0 && pos < NE) g_csrc[pos] = load_idx(eidx, e);
    }
}

// ---------------- segment mean: warp per node --------------------------------
__global__ void aggregate_kernel(const float* __restrict__ xin) {
    const float* __restrict__ p = xin ? xin : (const float*)g_h1;
    int gw   = (blockIdx.x * blockDim.x + threadIdx.x) >> 5;
    int lane = threadIdx.x & 31;
    if (gw >= NN) return;
    int r0 = g_rowptr[gw];
    int r1 = g_rowptr[gw + 1];
    float4 acc = make_float4(0.f, 0.f, 0.f, 0.f);
    for (int i = r0; i < r1; i++) {
        int s = g_csrc[i];
        float4 v = *(const float4*)(p + (size_t)s * F + lane * 4);
        acc.x += v.x; acc.y += v.y; acc.z += v.z; acc.w += v.w;
    }
    float inv = 1.0f / (float)max(r1 - r0, 1);
    acc.x *= inv; acc.y *= inv; acc.z *= inv; acc.w *= inv;
    *(float4*)(g_mean + (size_t)gw * F + lane * 4) = acc;
}

// ---------------- fp32 GEMM, FFMA2 inner loop, double-buffered smem ----------
// MODE 0: g_h1 = relu( g_mean@B1 + Aext@B2 + bias ), fp32 out, K=256
// MODE 1: g_h2 =       g_mean@B1 + g_h1@B2 + bias  , fp32 out, K=256
// MODE 2: g_ABh[:, 128*by : 128*by+128] = h2 @ (B1 + by*128*128), fp16 out, K=128
#define BM 128
#define BN 128
#define BK 8

template <int MODE>
__global__ __launch_bounds__(256)
void gemm128(const float* __restrict__ Aext,
             const float* __restrict__ B1, const float* __restrict__ B2,
             const float* __restrict__ bias, int M)
{
    constexpr int  Ktot   = (MODE <= 1) ? 256 : 128;
    constexpr int  NCHUNK = Ktot / BK;
    constexpr bool RELU   = (MODE == 0);
    constexpr bool BIAS   = (MODE <= 1);

    const float* A1 = (MODE <= 1) ? (const float*)g_mean : (const float*)g_h2;
    const float* A2 = (MODE == 0) ? Aext
                    : (MODE == 1) ? (const float*)g_h1 : nullptr;
    const float* Bw = (MODE == 2) ? (B1 + (size_t)blockIdx.y * 128 * 128) : B1;

    __shared__ float As[2][BK][BM];
    __shared__ float Bs[2][BK][BN];

    int tid = threadIdx.x;
    int m0  = blockIdx.x * BM;
    int tx  = tid & 15;
    int ty  = tid >> 4;

    // packed accumulators: acc2[i][jp] holds columns (2jp, 2jp+1) pairs
    unsigned long long acc2[8][4];
    const unsigned long long zz = pack2(0.f, 0.f);
#pragma unroll
    for (int i = 0; i < 8; i++)
#pragma unroll
        for (int jp = 0; jp < 4; jp++) acc2[i][jp] = zz;

    const int ar  = tid >> 1;
    const int ac4 = (tid & 1) * 4;
    const int br  = tid >> 5;
    const int bc4 = (tid & 31) * 4;
    const int gm_a = m0 + ar;

    float4 va, vb;
    auto load_chunk = [&](int ch) {
        int kc = ch * BK;
        const float* Ap; const float* Bp; int kk0;
        if (MODE >= 2 || kc < 128) { Ap = A1; Bp = Bw; kk0 = kc; }
        else                       { Ap = A2; Bp = B2; kk0 = kc - 128; }
        va = make_float4(0.f, 0.f, 0.f, 0.f);
        if (gm_a < M) va = *(const float4*)(Ap + (size_t)gm_a * 128 + kk0 + ac4);
        vb = *(const float4*)(Bp + (size_t)(kk0 + br) * 128 + bc4);
    };
    auto store_chunk = [&](int buf) {
        As[buf][ac4 + 0][ar] = va.x;
        As[buf][ac4 + 1][ar] = va.y;
        As[buf][ac4 + 2][ar] = va.z;
        As[buf][ac4 + 3][ar] = va.w;
        *(float4*)&Bs[buf][br][bc4] = vb;
    };

    load_chunk(0);
    store_chunk(0);
    __syncthreads();

    for (int ch = 0; ch < NCHUNK; ch++) {
        int cur = ch & 1;
        if (ch + 1 < NCHUNK) load_chunk(ch + 1);

#pragma unroll
        for (int kk = 0; kk < BK; kk++) {
            float a[8];
            *(float4*)&a[0] = *(float4*)&As[cur][kk][ty * 4];
            *(float4*)&a[4] = *(float4*)&As[cur][kk][64 + ty * 4];
            // b as packed pairs straight from smem (LDS.64)
            unsigned long long bp[4];
            bp[0] = *(const unsigned long long*)&Bs[cur][kk][tx * 4];
            bp[1] = *(const unsigned long long*)&Bs[cur][kk][tx * 4 + 2];
            bp[2] = *(const unsigned long long*)&Bs[cur][kk][64 + tx * 4];
            bp[3] = *(const unsigned long long*)&Bs[cur][kk][64 + tx * 4 + 2];
#pragma unroll
            for (int i = 0; i < 8; i++) {
                unsigned long long ad = pack2(a[i], a[i]);
#pragma unroll
                for (int jp = 0; jp < 4; jp++)
                    ffma2(acc2[i][jp], ad, bp[jp]);
            }
        }

        if (ch + 1 < NCHUNK) {
            store_chunk(cur ^ 1);
            __syncthreads();
        }
    }

    // epilogue
#pragma unroll
    for (int i = 0; i < 8; i++) {
        int r  = (i < 4) ? (ty * 4 + i) : (64 + ty * 4 + (i - 4));
        int gm = m0 + r;
        if (gm >= M) continue;
#pragma unroll
        for (int jh = 0; jh < 2; jh++) {
            int c = jh ? (64 + tx * 4) : (tx * 4);
            float4 v;
            unpack2(acc2[i][jh * 2 + 0], v.x, v.y);
            unpack2(acc2[i][jh * 2 + 1], v.z, v.w);
            if (BIAS) {
                v.x += bias[c + 0]; v.y += bias[c + 1];
                v.z += bias[c + 2]; v.w += bias[c + 3];
            }
            if (RELU) {
                v.x = fmaxf(v.x, 0.f); v.y = fmaxf(v.y, 0.f);
                v.z = fmaxf(v.z, 0.f); v.w = fmaxf(v.w, 0.f);
            }
            if (MODE <= 1) {
                float* C = (MODE == 0) ? (float*)g_h1 : (float*)g_h2;
                *(float4*)(C + (size_t)gm * 128 + c) = v;
            } else {
                __half* C = (__half*)g_ABh + blockIdx.y * 128;
                __half2 h01 = __floats2half2_rn(v.x, v.y);
                __half2 h23 = __floats2half2_rn(v.z, v.w);
                uint2 pack;
                pack.x = *(unsigned*)&h01;
                pack.y = *(unsigned*)&h23;
                *(uint2*)(C + (size_t)gm * 256 + c) = pack;
            }
        }
    }
}

// ---------------- edge classifier: warp per edge (fp16 AB table) -------------
__global__ __launch_bounds__(256)
void edge_kernel(const void* __restrict__ eidx,
                 const float* __restrict__ ea,
                 const float* __restrict__ Wc1,
                 const float* __restrict__ bc1,
                 const float* __restrict__ Wc2,
                 const float* __restrict__ bc2,
                 float* __restrict__ out)
{
    __shared__ float sWe0[128], sWe1[128], sWe2[128], sb[128], sw2[128];
    int tid = threadIdx.x;
    if (tid < 128) {
        sWe0[tid] = Wc1[256 * 128 + tid];
        sWe1[tid] = Wc1[257 * 128 + tid];
        sWe2[tid] = Wc1[258 * 128 + tid];
        sb[tid]   = bc1[tid];
        sw2[tid]  = Wc2[tid];
    }
    __syncthreads();

    int e = blockIdx.x * (blockDim.x >> 5) + (tid >> 5);
    if (e >= NE) return;
    int lane = tid & 31;
    int j = lane * 4;

    int s = load_idx(eidx, e);
    int d = load_idx(eidx, (long long)NE + e);

    uint2 av = *(const uint2*)(g_ABh + (size_t)s * 256 + j);
    uint2 bv = *(const uint2*)(g_ABh + (size_t)d * 256 + 128 + j);
    float2 a01 = __half22float2(*(__half2*)&av.x);
    float2 a23 = __half22float2(*(__half2*)&av.y);
    float2 b01 = __half22float2(*(__half2*)&bv.x);
    float2 b23 = __half22float2(*(__half2*)&bv.y);

    float4 w0 = *(const float4*)&sWe0[j];
    float4 w1 = *(const float4*)&sWe1[j];
    float4 w2 = *(const float4*)&sWe2[j];
    float4 bb = *(const float4*)&sb[j];
    float4 wc = *(const float4*)&sw2[j];

    float e0 = ea[(size_t)e * 3 + 0];
    float e1 = ea[(size_t)e * 3 + 1];
    float e2 = ea[(size_t)e * 3 + 2];

    float h, acc = 0.f;
    h = a01.x + b01.x + e0 * w0.x + e1 * w1.x + e2 * w2.x + bb.x;
    acc += fmaxf(h, 0.f) * wc.x;
    h = a01.y + b01.y + e0 * w0.y + e1 * w1.y + e2 * w2.y + bb.y;
    acc += fmaxf(h, 0.f) * wc.y;
    h = a23.x + b23.x + e0 * w0.z + e1 * w1.z + e2 * w2.z + bb.z;
    acc += fmaxf(h, 0.f) * wc.z;
    h = a23.y + b23.y + e0 * w0.w + e1 * w1.w + e2 * w2.w + bb.w;
    acc += fmaxf(h, 0.f) * wc.w;

#pragma unroll
    for (int off = 16; off > 0; off >>= 1)
        acc += __shfl_xor_sync(0xFFFFFFFFu, acc, off);

    if (lane == 0) out[e] = acc + bc2[0];
}

// ---------------- launch ------------------------------------------------------
extern "C" void kernel_launch(void* const* d_in, const int* in_sizes, int n_in,
                              void* d_out, int out_size)
{
    const float* x    = (const float*)d_in[0];
    const void*  eidx = d_in[1];
    const float* ea   = (const float*)d_in[2];
    const float* W1l  = (const float*)d_in[3];
    const float* b1l  = (const float*)d_in[4];
    const float* W1r  = (const float*)d_in[5];
    const float* W2l  = (const float*)d_in[6];
    const float* b2l  = (const float*)d_in[7];
    const float* W2r  = (const float*)d_in[8];
    const float* Wc1  = (const float*)d_in[9];
    const float* bc1  = (const float*)d_in[10];
    const float* Wc2  = (const float*)d_in[11];
    const float* bc2  = (const float*)d_in[12];
    float* out = (float*)d_out;

    const int SCAN_BLOCKS = (NN + 1023) / 1024;  // 49

    detect_kernel<<<1, 1>>>(eidx);

    zero_kernel<<<(NN + 255) / 256, 256>>>();
    hist_kernel<<<(NE + 255) / 256, 256>>>(eidx);
    scanA_kernel<<<SCAN_BLOCKS, 1024>>>();
    scanB_kernel<<<1, 64>>>(SCAN_BLOCKS);
    scanC_kernel<<<SCAN_BLOCKS, 1024>>>();
    scatter_kernel<<<(NE + 255) / 256, 256>>>(eidx);

    const int aggGrid  = (NN * 32 + 255) / 256;
    const int gemmGrid = (NN + BM - 1) / BM;  // 391

    aggregate_kernel<<<aggGrid, 256>>>(x);
    gemm128<0><<<gemmGrid, 256>>>(x, W1l, W1r, b1l, NN);

    aggregate_kernel<<<aggGrid, 256>>>(nullptr);
    gemm128<1><<<gemmGrid, 256>>>(nullptr, W2l, W2r, b2l, NN);

    gemm128<2><<<dim3(gemmGrid, 2), 256>>>(nullptr, Wc1, nullptr, nullptr, NN);

    edge_kernel<<<(NE * 32 + 255) / 256, 256>>>(eidx, ea, Wc1, bc1, Wc2, bc2, out);
}

// round 7
// speedup vs baseline: 1.5429x; 1.1649x over previous
#include <cuda_runtime.h>
#include <cuda_fp16.h>
#include <cuda_bf16.h>
#include <cstdint>

#define NN 50000
#define NE 800000
#define F  128

// ---------------- scratch (static device globals) ---------------------------
__device__ __align__(16) int    g_deg[NN];
__device__ __align__(16) int    g_cursor[NN];
__device__ __align__(16) int    g_rowptr[NN + 1];
__device__ __align__(16) int    g_csrc[NE];
__device__ __align__(16) float  g_h1[NN * F];
__device__ __align__(16) __half g_ABh[(size_t)NN * 256];
__device__ __align__(16) int    g_bsum[64];
__device__ __align__(16) int    g_boff[64];
__device__ int g_is64;

// bf16 hi/lo split operand tables
__device__ __align__(16) __nv_bfloat16 g_xhi[NN * F],  g_xlo[NN * F];
__device__ __align__(16) __nv_bfloat16 g_mhi[NN * F],  g_mlo[NN * F];
__device__ __align__(16) __nv_bfloat16 g_h1hi[NN * F], g_h1lo[NN * F];
__device__ __align__(16) __nv_bfloat16 g_h2hi[NN * F], g_h2lo[NN * F];
// weights transposed+split: wt[n][k]; wt1 @0 (K=256), wt2 @32768 (K=256), wtc @65536 (2x 128x128)
__device__ __align__(16) __nv_bfloat16 g_wt_hi[98304], g_wt_lo[98304];

// ---------------- helpers -----------------------------------------------------
__device__ __forceinline__ uint32_t sm32(const void* p) {
    uint32_t a;
    asm("{ .reg .u64 t; cvta.to.shared.u64 t, %1; cvt.u32.u64 %0, t; }"
        : "=r"(a) : "l"(p));
    return a;
}

__device__ __forceinline__ void ldm_x4(uint32_t (&r)[4], uint32_t addr) {
    asm volatile("ldmatrix.sync.aligned.m8n8.x4.shared.b16 {%0,%1,%2,%3}, [%4];"
        : "=r"(r[0]), "=r"(r[1]), "=r"(r[2]), "=r"(r[3]) : "r"(addr));
}
__device__ __forceinline__ void ldm_x2(uint32_t (&r)[2], uint32_t addr) {
    asm volatile("ldmatrix.sync.aligned.m8n8.x2.shared.b16 {%0,%1}, [%2];"
        : "=r"(r[0]), "=r"(r[1]) : "r"(addr));
}
__device__ __forceinline__ void mma16816(float (&d)[4], const uint32_t (&a)[4],
                                         const uint32_t (&b)[2]) {
    asm volatile("mma.sync.aligned.m16n8k16.row.col.f32.bf16.bf16.f32 "
        "{%0,%1,%2,%3}, {%4,%5,%6,%7}, {%8,%9}, {%0,%1,%2,%3};"
        : "+f"(d[0]), "+f"(d[1]), "+f"(d[2]), "+f"(d[3])
        : "r"(a[0]), "r"(a[1]), "r"(a[2]), "r"(a[3]), "r"(b[0]), "r"(b[1]));
}

__device__ __forceinline__ unsigned short bfu(__nv_bfloat16 h) {
    return __bfloat16_as_ushort(h);
}
__device__ __forceinline__ void split4(float4 v, uint2& hi, uint2& lo) {
    __nv_bfloat16 h0 = __float2bfloat16(v.x), h1 = __float2bfloat16(v.y);
    __nv_bfloat16 h2 = __float2bfloat16(v.z), h3 = __float2bfloat16(v.w);
    float r0 = v.x - __bfloat162float(h0), r1 = v.y - __bfloat162float(h1);
    float r2 = v.z - __bfloat162float(h2), r3 = v.w - __bfloat162float(h3);
    __nv_bfloat16 l0 = __float2bfloat16(r0), l1 = __float2bfloat16(r1);
    __nv_bfloat16 l2 = __float2bfloat16(r2), l3 = __float2bfloat16(r3);
    hi.x = (unsigned)bfu(h0) | ((unsigned)bfu(h1) << 16);
    hi.y = (unsigned)bfu(h2) | ((unsigned)bfu(h3) << 16);
    lo.x = (unsigned)bfu(l0) | ((unsigned)bfu(l1) << 16);
    lo.y = (unsigned)bfu(l2) | ((unsigned)bfu(l3) << 16);
}
__device__ __forceinline__ void split2(float x, float y, unsigned& hi, unsigned& lo) {
    __nv_bfloat16 h0 = __float2bfloat16(x), h1 = __float2bfloat16(y);
    float r0 = x - __bfloat162float(h0), r1 = y - __bfloat162float(h1);
    hi = (unsigned)bfu(h0) | ((unsigned)bfu(h1) << 16);
    lo = (unsigned)bfu(__float2bfloat16(r0)) |
         ((unsigned)bfu(__float2bfloat16(r1)) << 16);
}

// ---------------- index decode --------------------------------------------------
__device__ __forceinline__ int load_idx(const void* p, long long pos) {
    int v;
    if (g_is64) v = (int)((const long long*)p)[pos];
    else        v = ((const int*)p)[pos];
    return min(max(v, 0), NN - 1);
}

// ---------------- fused setup: detect + zero + weight prep + x convert ----------
__global__ void setup_kernel(const void* __restrict__ eidx,
                             const float* __restrict__ x,
                             const float* __restrict__ W1l, const float* __restrict__ W1r,
                             const float* __restrict__ W2l, const float* __restrict__ W2r,
                             const float* __restrict__ Wc1)
{
    long long gid = (long long)blockIdx.x * blockDim.x + threadIdx.x;
    if (gid == 0) {
        const int* w = (const int*)eidx;
        int is64 = 1;
        for (int i = 1; i < 256; i += 2)
            if (w[i] != 0) { is64 = 0; break; }
        g_is64 = is64;
    }
    if (gid < NN) { g_deg[gid] = 0; g_cursor[gid] = 0; }

    long long wI = gid - NN;
    if (wI >= 0 && wI < 98304) {
        float v;
        if (wI < 32768) {
            int n = (int)(wI >> 8), k = (int)(wI & 255);
            v = (k < 128) ? W1l[k * 128 + n] : W1r[(k - 128) * 128 + n];
        } else if (wI < 65536) {
            long long l = wI - 32768;
            int n = (int)(l >> 8), k = (int)(l & 255);
            v = (k < 128) ? W2l[k * 128 + n] : W2r[(k - 128) * 128 + n];
        } else {
            long long l = wI - 65536;
            int by = (int)(l >> 14), r = (int)(l & 16383);
            int n = r >> 7, k = r & 127;
            v = Wc1[(size_t)(by * 128 + k) * 128 + n];
        }
        __nv_bfloat16 h = __float2bfloat16(v);
        g_wt_hi[wI] = h;
        g_wt_lo[wI] = __float2bfloat16(v - __bfloat162float(h));
    }

    long long cI = gid - NN - 98304;
    if (cI >= 0 && cI < (long long)NN * 32) {
        float4 v = *(const float4*)(x + cI * 4);
        uint2 hi, lo;
        split4(v, hi, lo);
        *(uint2*)(g_xhi + cI * 4) = hi;
        *(uint2*)(g_xlo + cI * 4) = lo;
    }
}

// ---------------- CSR build ------------------------------------------------------
__global__ void hist_kernel(const void* __restrict__ eidx) {
    int e = blockIdx.x * blockDim.x + threadIdx.x;
    if (e < NE) atomicAdd(&g_deg[load_idx(eidx, (long long)NE + e)], 1);
}

__global__ void scanA_kernel() {
    __shared__ int warp_sums[32];
    int b = blockIdx.x, t = threadIdx.x;
    int i = b * 1024 + t;
    int lane = t & 31, w = t >> 5;
    int v = (i < NN) ? g_deg[i] : 0;
    int s = v;
#pragma unroll
    for (int off = 1; off < 32; off <<= 1) {
        int n = __shfl_up_sync(0xFFFFFFFFu, s, off);
        if (lane >= off) s += n;
    }
    if (lane == 31) warp_sums[w] = s;
    __syncthreads();
    if (w == 0) {
        int ws = warp_sums[lane];
#pragma unroll
        for (int off = 1; off < 32; off <<= 1) {
            int n = __shfl_up_sync(0xFFFFFFFFu, ws, off);
            if (lane >= off) ws += n;
        }
        warp_sums[lane] = ws;
    }
    __syncthreads();
    int woff = (w == 0) ? 0 : warp_sums[w - 1];
    int incl = s + woff;
    if (i < NN) g_rowptr[i] = incl - v;
    if (t == 1023) g_bsum[b] = incl;
}

__global__ void scanB_kernel(int nblocks) {
    __shared__ int sh[64];
    int t = threadIdx.x;
    int v = (t < nblocks) ? g_bsum[t] : 0;
    sh[t] = v;
    __syncthreads();
    for (int off = 1; off < 64; off <<= 1) {
        int n = (t >= off) ? sh[t - off] : 0;
        __syncthreads();
        sh[t] += n;
        __syncthreads();
    }
    g_boff[t] = sh[t] - v;
    if (t == 0) g_rowptr[NN] = NE;
}

__global__ void scanC_kernel() {
    int i = blockIdx.x * 1024 + threadIdx.x;
    if (i < NN) g_rowptr[i] += g_boff[blockIdx.x];
}

__global__ void scatter_kernel(const void* __restrict__ eidx) {
    int e = blockIdx.x * blockDim.x + threadIdx.x;
    if (e < NE) {
        int d = load_idx(eidx, (long long)NE + e);
        int pos = g_rowptr[d] + atomicAdd(&g_cursor[d], 1);
        if (pos >= 0 && pos < NE) g_csrc[pos] = load_idx(eidx, e);
    }
}

// ---------------- segment mean: warp per node -> bf16 hi/lo ----------------------
__global__ void aggregate_kernel(const float* __restrict__ xin) {
    const float* __restrict__ p = xin ? xin : (const float*)g_h1;
    int gw   = (blockIdx.x * blockDim.x + threadIdx.x) >> 5;
    int lane = threadIdx.x & 31;
    if (gw >= NN) return;
    int r0 = g_rowptr[gw];
    int r1 = g_rowptr[gw + 1];
    float4 acc = make_float4(0.f, 0.f, 0.f, 0.f);
    for (int i = r0; i < r1; i++) {
        int s = g_csrc[i];
        float4 v = *(const float4*)(p + (size_t)s * F + lane * 4);
        acc.x += v.x; acc.y += v.y; acc.z += v.z; acc.w += v.w;
    }
    float inv = 1.0f / (float)max(r1 - r0, 1);
    acc.x *= inv; acc.y *= inv; acc.z *= inv; acc.w *= inv;
    uint2 hi, lo;
    split4(acc, hi, lo);
    *(uint2*)(g_mhi + (size_t)gw * F + lane * 4) = hi;
    *(uint2*)(g_mlo + (size_t)gw * F + lane * 4) = lo;
}

// ---------------- HMMA split-bf16 GEMM --------------------------------------------
// MODE 0: h1 = relu(mean@W1 + x@W1r + b)  -> g_h1 fp32 + g_h1hi/lo, K=256
// MODE 1: h2 = mean@W2 + h1@W2r + b       -> g_h2hi/lo, K=256
// MODE 2: ABh[:, by*128..] = h2 @ WcH     -> g_ABh fp16, K=128, grid.y=2
#define SAPAD 40   // padded row stride (elems): 80B rows, 16B aligned, conflict-free

template <int MODE>
__global__ __launch_bounds__(512)
void mma_gemm(const float* __restrict__ bias, int M)
{
    constexpr int NCHUNK = (MODE <= 1) ? 8 : 4;   // K-chunks of 32
    constexpr int KTOT   = (MODE <= 1) ? 256 : 128;
    const int wtoff = (MODE == 0) ? 0 : (MODE == 1) ? 32768
                     : 65536 + (int)blockIdx.y * 16384;

    __shared__ __nv_bfloat16 sAhi[128][SAPAD], sAlo[128][SAPAD];
    __shared__ __nv_bfloat16 sBhi[128][SAPAD], sBlo[128][SAPAD];

    int tid  = threadIdx.x;
    int wid  = tid >> 5, lane = tid & 31;
    int m0   = blockIdx.x * 128;
    int wm   = wid >> 2, wn = wid & 3;           // 4x4 warp grid
    int mb   = wm * 32,  nb = wn * 32;

    float acc[2][4][4];
#pragma unroll
    for (int mi = 0; mi < 2; mi++)
#pragma unroll
        for (int ni = 0; ni < 4; ni++)
#pragma unroll
            for (int q = 0; q < 4; q++) acc[mi][ni][q] = 0.f;

    // smem fill mapping: one uint4 (8 bf16) per thread per tile
    const int frow = tid >> 2;            // 0..127
    const int fseg = (tid & 3) * 8;       // 0,8,16,24
    const int gmf  = m0 + frow;

    // ldmatrix source addresses (per warp)
    // A: rows mb+mi*16+(lane&15), col (lane>>4)*8 + ks*16
    const int a_r = (lane & 15);
    const int a_c = (lane >> 4) * 8;
    // B: rows nb+ni*8+(lane&7), col ((lane>>3)&1)*8 + ks*16
    const int b_r = (lane & 7);
    const int b_c = ((lane >> 3) & 1) * 8;

    for (int ch = 0; ch < NCHUNK; ch++) {
        const __nv_bfloat16 *ah, *al;
        int kk0;
        if (MODE == 2)      { ah = g_h2hi; al = g_h2lo; kk0 = ch * 32; }
        else if (ch < 4)    { ah = g_mhi;  al = g_mlo;  kk0 = ch * 32; }
        else if (MODE == 0) { ah = g_xhi;  al = g_xlo;  kk0 = (ch - 4) * 32; }
        else                { ah = g_h1hi; al = g_h1lo; kk0 = (ch - 4) * 32; }
        int kkw = ch * 32;

        // fill tiles
        {
            uint4 z = make_uint4(0, 0, 0, 0);
            uint4 vh = z, vl = z;
            if (gmf < M) {
                vh = *(const uint4*)(ah + (size_t)gmf * F + kk0 + fseg);
                vl = *(const uint4*)(al + (size_t)gmf * F + kk0 + fseg);
            }
            *(uint4*)&sAhi[frow][fseg] = vh;
            *(uint4*)&sAlo[frow][fseg] = vl;
            *(uint4*)&sBhi[frow][fseg] =
                *(const uint4*)(g_wt_hi + wtoff + (size_t)frow * KTOT + kkw + fseg);
            *(uint4*)&sBlo[frow][fseg] =
                *(const uint4*)(g_wt_lo + wtoff + (size_t)frow * KTOT + kkw + fseg);
        }
        __syncthreads();

#pragma unroll
        for (int ks = 0; ks < 2; ks++) {
            uint32_t ahf[2][4], alf[2][4], bhf[4][2], blf[4][2];
#pragma unroll
            for (int mi = 0; mi < 2; mi++) {
                uint32_t addr_h = sm32(&sAhi[mb + mi * 16 + a_r][ks * 16 + a_c]);
                uint32_t addr_l = sm32(&sAlo[mb + mi * 16 + a_r][ks * 16 + a_c]);
                ldm_x4(ahf[mi], addr_h);
                ldm_x4(alf[mi], addr_l);
            }
#pragma unroll
            for (int ni = 0; ni < 4; ni++) {
                uint32_t addr_h = sm32(&sBhi[nb + ni * 8 + b_r][ks * 16 + b_c]);
                uint32_t addr_l = sm32(&sBlo[nb + ni * 8 + b_r][ks * 16 + b_c]);
                ldm_x2(bhf[ni], addr_h);
                ldm_x2(blf[ni], addr_l);
            }
#pragma unroll
            for (int mi = 0; mi < 2; mi++)
#pragma unroll
                for (int ni = 0; ni < 4; ni++) {
                    mma16816(acc[mi][ni], ahf[mi], bhf[ni]);
                    mma16816(acc[mi][ni], ahf[mi], blf[ni]);
                    mma16816(acc[mi][ni], alf[mi], bhf[ni]);
                }
        }
        __syncthreads();
    }

    // epilogue: d-frag mapping row = t/4 (+8), col = (t%4)*2 (+1)
    const int trow = lane >> 2;
    const int tcol = (lane & 3) * 2;
#pragma unroll
    for (int mi = 0; mi < 2; mi++) {
#pragma unroll
        for (int half = 0; half < 2; half++) {
            int m = m0 + mb + mi * 16 + trow + half * 8;
            if (m >= M) continue;
#pragma unroll
            for (int ni = 0; ni < 4; ni++) {
                int col = nb + ni * 8 + tcol;
                float vx = acc[mi][ni][half * 2 + 0];
                float vy = acc[mi][ni][half * 2 + 1];
                if (MODE <= 1) { vx += bias[col]; vy += bias[col + 1]; }
                if (MODE == 0) { vx = fmaxf(vx, 0.f); vy = fmaxf(vy, 0.f); }
                if (MODE == 0) {
                    *(float2*)(g_h1 + (size_t)m * F + col) = make_float2(vx, vy);
                    unsigned hi, lo;
                    split2(vx, vy, hi, lo);
                    *(unsigned*)(g_h1hi + (size_t)m * F + col) = hi;
                    *(unsigned*)(g_h1lo + (size_t)m * F + col) = lo;
                } else if (MODE == 1) {
                    unsigned hi, lo;
                    split2(vx, vy, hi, lo);
                    *(unsigned*)(g_h2hi + (size_t)m * F + col) = hi;
                    *(unsigned*)(g_h2lo + (size_t)m * F + col) = lo;
                } else {
                    __half2 h = __floats2half2_rn(vx, vy);
                    *(__half2*)(g_ABh + (size_t)m * 256 + blockIdx.y * 128 + col) = h;
                }
            }
        }
    }
}

// ---------------- edge classifier: warp per edge (fp16 AB table) -----------------
__global__ __launch_bounds__(256)
void edge_kernel(const void* __restrict__ eidx,
                 const float* __restrict__ ea,
                 const float* __restrict__ Wc1,
                 const float* __restrict__ bc1,
                 const float* __restrict__ Wc2,
                 const float* __restrict__ bc2,
                 float* __restrict__ out)
{
    __shared__ float sWe0[128], sWe1[128], sWe2[128], sb[128], sw2[128];
    int tid = threadIdx.x;
    if (tid < 128) {
        sWe0[tid] = Wc1[256 * 128 + tid];
        sWe1[tid] = Wc1[257 * 128 + tid];
        sWe2[tid] = Wc1[258 * 128 + tid];
        sb[tid]   = bc1[tid];
        sw2[tid]  = Wc2[tid];
    }
    __syncthreads();

    int e = blockIdx.x * (blockDim.x >> 5) + (tid >> 5);
    if (e >= NE) return;
    int lane = tid & 31;
    int j = lane * 4;

    int s = load_idx(eidx, e);
    int d = load_idx(eidx, (long long)NE + e);

    uint2 av = *(const uint2*)(g_ABh + (size_t)s * 256 + j);
    uint2 bv = *(const uint2*)(g_ABh + (size_t)d * 256 + 128 + j);
    float2 a01 = __half22float2(*(__half2*)&av.x);
    float2 a23 = __half22float2(*(__half2*)&av.y);
    float2 b01 = __half22float2(*(__half2*)&bv.x);
    float2 b23 = __half22float2(*(__half2*)&bv.y);

    float4 w0 = *(const float4*)&sWe0[j];
    float4 w1 = *(const float4*)&sWe1[j];
    float4 w2 = *(const float4*)&sWe2[j];
    float4 bb = *(const float4*)&sb[j];
    float4 wc = *(const float4*)&sw2[j];

    float e0 = ea[(size_t)e * 3 + 0];
    float e1 = ea[(size_t)e * 3 + 1];
    float e2 = ea[(size_t)e * 3 + 2];

    float h, acc = 0.f;
    h = a01.x + b01.x + e0 * w0.x + e1 * w1.x + e2 * w2.x + bb.x;
    acc += fmaxf(h, 0.f) * wc.x;
    h = a01.y + b01.y + e0 * w0.y + e1 * w1.y + e2 * w2.y + bb.y;
    acc += fmaxf(h, 0.f) * wc.y;
    h = a23.x + b23.x + e0 * w0.z + e1 * w1.z + e2 * w2.z + bb.z;
    acc += fmaxf(h, 0.f) * wc.z;
    h = a23.y + b23.y + e0 * w0.w + e1 * w1.w + e2 * w2.w + bb.w;
    acc += fmaxf(h, 0.f) * wc.w;

#pragma unroll
    for (int off = 16; off > 0; off >>= 1)
        acc += __shfl_xor_sync(0xFFFFFFFFu, acc, off);

    if (lane == 0) out[e] = acc + bc2[0];
}

// ---------------- launch -----------------------------------------------------------
extern "C" void kernel_launch(void* const* d_in, const int* in_sizes, int n_in,
                              void* d_out, int out_size)
{
    const float* x    = (const float*)d_in[0];
    const void*  eidx = d_in[1];
    const float* ea   = (const float*)d_in[2];
    const float* W1l  = (const float*)d_in[3];
    const float* b1l  = (const float*)d_in[4];
    const float* W1r  = (const float*)d_in[5];
    const float* W2l  = (const float*)d_in[6];
    const float* b2l  = (const float*)d_in[7];
    const float* W2r  = (const float*)d_in[8];
    const float* Wc1  = (const float*)d_in[9];
    const float* bc1  = (const float*)d_in[10];
    const float* Wc2  = (const float*)d_in[11];
    const float* bc2  = (const float*)d_in[12];
    float* out = (float*)d_out;

    const int SCAN_BLOCKS = (NN + 1023) / 1024;  // 49

    long long setup_threads = (long long)NN + 98304 + (long long)NN * 32;
    int setup_grid = (int)((setup_threads + 255) / 256);
    setup_kernel<<<setup_grid, 256>>>(eidx, x, W1l, W1r, W2l, W2r, Wc1);

    hist_kernel<<<(NE + 255) / 256, 256>>>(eidx);
    scanA_kernel<<<SCAN_BLOCKS, 1024>>>();
    scanB_kernel<<<1, 64>>>(SCAN_BLOCKS);
    scanC_kernel<<<SCAN_BLOCKS, 1024>>>();
    scatter_kernel<<<(NE + 255) / 256, 256>>>(eidx);

    const int aggGrid  = (NN * 32 + 255) / 256;
    const int gemmGrid = (NN + 127) / 128;       // 391

    aggregate_kernel<<<aggGrid, 256>>>(x);
    mma_gemm<0><<<gemmGrid, 512>>>(b1l, NN);

    aggregate_kernel<<<aggGrid, 256>>>(nullptr);
    mma_gemm<1><<<gemmGrid, 512>>>(b2l, NN);

    mma_gemm<2><<<dim3(gemmGrid, 2), 512>>>(nullptr, NN);

    edge_kernel<<<(NE * 32 + 255) / 256, 256>>>(eidx, ea, Wc1, bc1, Wc2, bc2, out);
}

// round 8
// speedup vs baseline: 1.5829x; 1.0259x over previous
#include <cuda_runtime.h>
#include <cuda_fp16.h>
#include <cuda_bf16.h>
#include <cstdint>

#define NN 50000
#define NE 800000
#define F  128

// ---------------- scratch (static device globals) ---------------------------
__device__ __align__(16) int    g_deg[NN];
__device__ __align__(16) int    g_cursor[NN];
__device__ __align__(16) int    g_rowptr[NN + 1];
__device__ __align__(16) int    g_csrc[NE];
__device__ __align__(16) __half g_ABh[(size_t)NN * 256];
__device__ __align__(16) int    g_bsum[64];
__device__ __align__(16) int    g_boff[64];
__device__ int g_is64;

// fp16 gather tables for aggregation
__device__ __align__(16) __half g_x16[NN * F];
__device__ __align__(16) __half g_h1h16[NN * F];
// bf16 hi/lo split operand tables (GEMM A operands)
__device__ __align__(16) __nv_bfloat16 g_xhi[NN * F],  g_xlo[NN * F];
__device__ __align__(16) __nv_bfloat16 g_mhi[NN * F],  g_mlo[NN * F];
__device__ __align__(16) __nv_bfloat16 g_h1hi[NN * F], g_h1lo[NN * F];
__device__ __align__(16) __nv_bfloat16 g_h2hi[NN * F], g_h2lo[NN * F];
// weights transposed+split: wt[n][k]; wt1 @0 (K=256), wt2 @32768 (K=256), wtc @65536 (2x 128x128)
__device__ __align__(16) __nv_bfloat16 g_wt_hi[98304], g_wt_lo[98304];

// ---------------- helpers -----------------------------------------------------
__device__ __forceinline__ uint32_t sm32(const void* p) {
    uint32_t a;
    asm("{ .reg .u64 t; cvta.to.shared.u64 t, %1; cvt.u32.u64 %0, t; }"
        : "=r"(a) : "l"(p));
    return a;
}

__device__ __forceinline__ void ldm_x4(uint32_t (&r)[4], uint32_t addr) {
    asm volatile("ldmatrix.sync.aligned.m8n8.x4.shared.b16 {%0,%1,%2,%3}, [%4];"
        : "=r"(r[0]), "=r"(r[1]), "=r"(r[2]), "=r"(r[3]) : "r"(addr));
}
__device__ __forceinline__ void ldm_x2(uint32_t (&r)[2], uint32_t addr) {
    asm volatile("ldmatrix.sync.aligned.m8n8.x2.shared.b16 {%0,%1}, [%2];"
        : "=r"(r[0]), "=r"(r[1]) : "r"(addr));
}
__device__ __forceinline__ void mma16816(float (&d)[4], const uint32_t (&a)[4],
                                         const uint32_t (&b)[2]) {
    asm volatile("mma.sync.aligned.m16n8k16.row.col.f32.bf16.bf16.f32 "
        "{%0,%1,%2,%3}, {%4,%5,%6,%7}, {%8,%9}, {%0,%1,%2,%3};"
        : "+f"(d[0]), "+f"(d[1]), "+f"(d[2]), "+f"(d[3])
        : "r"(a[0]), "r"(a[1]), "r"(a[2]), "r"(a[3]), "r"(b[0]), "r"(b[1]));
}

__device__ __forceinline__ unsigned short bfu(__nv_bfloat16 h) {
    return __bfloat16_as_ushort(h);
}
__device__ __forceinline__ void split4(float4 v, uint2& hi, uint2& lo) {
    __nv_bfloat16 h0 = __float2bfloat16(v.x), h1 = __float2bfloat16(v.y);
    __nv_bfloat16 h2 = __float2bfloat16(v.z), h3 = __float2bfloat16(v.w);
    float r0 = v.x - __bfloat162float(h0), r1 = v.y - __bfloat162float(h1);
    float r2 = v.z - __bfloat162float(h2), r3 = v.w - __bfloat162float(h3);
    __nv_bfloat16 l0 = __float2bfloat16(r0), l1 = __float2bfloat16(r1);
    __nv_bfloat16 l2 = __float2bfloat16(r2), l3 = __float2bfloat16(r3);
    hi.x = (unsigned)bfu(h0) | ((unsigned)bfu(h1) << 16);
    hi.y = (unsigned)bfu(h2) | ((unsigned)bfu(h3) << 16);
    lo.x = (unsigned)bfu(l0) | ((unsigned)bfu(l1) << 16);
    lo.y = (unsigned)bfu(l2) | ((unsigned)bfu(l3) << 16);
}
__device__ __forceinline__ void split2(float x, float y, unsigned& hi, unsigned& lo) {
    __nv_bfloat16 h0 = __float2bfloat16(x), h1 = __float2bfloat16(y);
    float r0 = x - __bfloat162float(h0), r1 = y - __bfloat162float(h1);
    hi = (unsigned)bfu(h0) | ((unsigned)bfu(h1) << 16);
    lo = (unsigned)bfu(__float2bfloat16(r0)) |
         ((unsigned)bfu(__float2bfloat16(r1)) << 16);
}

// ---------------- index decode --------------------------------------------------
__device__ __forceinline__ int load_idx(const void* p, long long pos) {
    int v;
    if (g_is64) v = (int)((const long long*)p)[pos];
    else        v = ((const int*)p)[pos];
    return min(max(v, 0), NN - 1);
}

// ---------------- fused setup: detect + zero + weight prep + x convert ----------
__global__ void setup_kernel(const void* __restrict__ eidx,
                             const float* __restrict__ x,
                             const float* __restrict__ W1l, const float* __restrict__ W1r,
                             const float* __restrict__ W2l, const float* __restrict__ W2r,
                             const float* __restrict__ Wc1)
{
    long long gid = (long long)blockIdx.x * blockDim.x + threadIdx.x;
    if (gid == 0) {
        const int* w = (const int*)eidx;
        int is64 = 1;
        for (int i = 1; i < 256; i += 2)
            if (w[i] != 0) { is64 = 0; break; }
        g_is64 = is64;
    }
    if (gid < NN) { g_deg[gid] = 0; g_cursor[gid] = 0; }

    long long wI = gid - NN;
    if (wI >= 0 && wI < 98304) {
        float v;
        if (wI < 32768) {
            int n = (int)(wI >> 8), k = (int)(wI & 255);
            v = (k < 128) ? W1l[k * 128 + n] : W1r[(k - 128) * 128 + n];
        } else if (wI < 65536) {
            long long l = wI - 32768;
            int n = (int)(l >> 8), k = (int)(l & 255);
            v = (k < 128) ? W2l[k * 128 + n] : W2r[(k - 128) * 128 + n];
        } else {
            long long l = wI - 65536;
            int by = (int)(l >> 14), r = (int)(l & 16383);
            int n = r >> 7, k = r & 127;
            v = Wc1[(size_t)(by * 128 + k) * 128 + n];
        }
        __nv_bfloat16 h = __float2bfloat16(v);
        g_wt_hi[wI] = h;
        g_wt_lo[wI] = __float2bfloat16(v - __bfloat162float(h));
    }

    long long cI = gid - NN - 98304;   // x convert: one float4 per thread
    if (cI >= 0 && cI < (long long)NN * 32) {
        float4 v = *(const float4*)(x + cI * 4);
        uint2 hi, lo;
        split4(v, hi, lo);
        *(uint2*)(g_xhi + cI * 4) = hi;
        *(uint2*)(g_xlo + cI * 4) = lo;
        __half2 f01 = __floats2half2_rn(v.x, v.y);
        __half2 f23 = __floats2half2_rn(v.z, v.w);
        uint2 pk;
        pk.x = *(unsigned*)&f01;
        pk.y = *(unsigned*)&f23;
        *(uint2*)(g_x16 + cI * 4) = pk;
    }
}

// ---------------- CSR build ------------------------------------------------------
__global__ void hist_kernel(const void* __restrict__ eidx) {
    int e = blockIdx.x * blockDim.x + threadIdx.x;
    if (e < NE) atomicAdd(&g_deg[load_idx(eidx, (long long)NE + e)], 1);
}

__global__ void scanA_kernel() {
    __shared__ int warp_sums[32];
    int b = blockIdx.x, t = threadIdx.x;
    int i = b * 1024 + t;
    int lane = t & 31, w = t >> 5;
    int v = (i < NN) ? g_deg[i] : 0;
    int s = v;
#pragma unroll
    for (int off = 1; off < 32; off <<= 1) {
        int n = __shfl_up_sync(0xFFFFFFFFu, s, off);
        if (lane >= off) s += n;
    }
    if (lane == 31) warp_sums[w] = s;
    __syncthreads();
    if (w == 0) {
        int ws = warp_sums[lane];
#pragma unroll
        for (int off = 1; off < 32; off <<= 1) {
            int n = __shfl_up_sync(0xFFFFFFFFu, ws, off);
            if (lane >= off) ws += n;
        }
        warp_sums[lane] = ws;
    }
    __syncthreads();
    int woff = (w == 0) ? 0 : warp_sums[w - 1];
    int incl = s + woff;
    if (i < NN) g_rowptr[i] = incl - v;
    if (t == 1023) g_bsum[b] = incl;
}

__global__ void scanB_kernel(int nblocks) {
    __shared__ int sh[64];
    int t = threadIdx.x;
    int v = (t < nblocks) ? g_bsum[t] : 0;
    sh[t] = v;
    __syncthreads();
    for (int off = 1; off < 64; off <<= 1) {
        int n = (t >= off) ? sh[t - off] : 0;
        __syncthreads();
        sh[t] += n;
        __syncthreads();
    }
    g_boff[t] = sh[t] - v;
    if (t == 0) g_rowptr[NN] = NE;
}

__global__ void scanC_kernel() {
    int i = blockIdx.x * 1024 + threadIdx.x;
    if (i < NN) g_rowptr[i] += g_boff[blockIdx.x];
}

__global__ void scatter_kernel(const void* __restrict__ eidx) {
    int e = blockIdx.x * blockDim.x + threadIdx.x;
    if (e < NE) {
        int d = load_idx(eidx, (long long)NE + e);
        int pos = g_rowptr[d] + atomicAdd(&g_cursor[d], 1);
        if (pos >= 0 && pos < NE) g_csrc[pos] = load_idx(eidx, e);
    }
}

// ---------------- segment mean: warp per node, fp16 gather -> bf16 hi/lo ---------
template <int WHICH>   // 0: gather g_x16, 1: gather g_h1h16
__global__ void aggregate_kernel() {
    const __half* __restrict__ p = (WHICH == 0) ? g_x16 : g_h1h16;
    int gw   = (blockIdx.x * blockDim.x + threadIdx.x) >> 5;
    int lane = threadIdx.x & 31;
    if (gw >= NN) return;
    int r0 = g_rowptr[gw];
    int r1 = g_rowptr[gw + 1];
    float4 acc = make_float4(0.f, 0.f, 0.f, 0.f);
    for (int i = r0; i < r1; i++) {
        int s = g_csrc[i];
        uint2 v = *(const uint2*)(p + (size_t)s * F + lane * 4);
        float2 v01 = __half22float2(*(__half2*)&v.x);
        float2 v23 = __half22float2(*(__half2*)&v.y);
        acc.x += v01.x; acc.y += v01.y; acc.z += v23.x; acc.w += v23.y;
    }
    float inv = 1.0f / (float)max(r1 - r0, 1);
    acc.x *= inv; acc.y *= inv; acc.z *= inv; acc.w *= inv;
    uint2 hi, lo;
    split4(acc, hi, lo);
    *(uint2*)(g_mhi + (size_t)gw * F + lane * 4) = hi;
    *(uint2*)(g_mlo + (size_t)gw * F + lane * 4) = lo;
}

// ---------------- HMMA split-bf16 GEMM --------------------------------------------
// MODE 0: h1 = relu(mean@W1 + x@W1r + b)  -> g_h1h16 fp16 + g_h1hi/lo, K=256
// MODE 1: h2 = mean@W2 + h1@W2r + b       -> g_h2hi/lo, K=256
// MODE 2: ABh[:, by*128..] = h2 @ WcH     -> g_ABh fp16, K=128, grid.y=2
#define SAPAD 40   // padded row stride (elems): 80B rows, 16B aligned, conflict-free

template <int MODE>
__global__ __launch_bounds__(512)
void mma_gemm(const float* __restrict__ bias, int M)
{
    constexpr int NCHUNK = (MODE <= 1) ? 8 : 4;   // K-chunks of 32
    constexpr int KTOT   = (MODE <= 1) ? 256 : 128;
    const int wtoff = (MODE == 0) ? 0 : (MODE == 1) ? 32768
                     : 65536 + (int)blockIdx.y * 16384;

    __shared__ __nv_bfloat16 sAhi[128][SAPAD], sAlo[128][SAPAD];
    __shared__ __nv_bfloat16 sBhi[128][SAPAD], sBlo[128][SAPAD];

    int tid  = threadIdx.x;
    int wid  = tid >> 5, lane = tid & 31;
    int m0   = blockIdx.x * 128;
    int wm   = wid >> 2, wn = wid & 3;           // 4x4 warp grid
    int mb   = wm * 32,  nb = wn * 32;

    float acc[2][4][4];
#pragma unroll
    for (int mi = 0; mi < 2; mi++)
#pragma unroll
        for (int ni = 0; ni < 4; ni++)
#pragma unroll
            for (int q = 0; q < 4; q++) acc[mi][ni][q] = 0.f;

    const int frow = tid >> 2;            // 0..127
    const int fseg = (tid & 3) * 8;       // 0,8,16,24
    const int gmf  = m0 + frow;

    const int a_r = (lane & 15);
    const int a_c = (lane >> 4) * 8;
    const int b_r = (lane & 7);
    const int b_c = ((lane >> 3) & 1) * 8;

    for (int ch = 0; ch < NCHUNK; ch++) {
        const __nv_bfloat16 *ah, *al;
        int kk0;
        if (MODE == 2)      { ah = g_h2hi; al = g_h2lo; kk0 = ch * 32; }
        else if (ch < 4)    { ah = g_mhi;  al = g_mlo;  kk0 = ch * 32; }
        else if (MODE == 0) { ah = g_xhi;  al = g_xlo;  kk0 = (ch - 4) * 32; }
        else                { ah = g_h1hi; al = g_h1lo; kk0 = (ch - 4) * 32; }
        int kkw = ch * 32;

        {
            uint4 z = make_uint4(0, 0, 0, 0);
            uint4 vh = z, vl = z;
            if (gmf < M) {
                vh = *(const uint4*)(ah + (size_t)gmf * F + kk0 + fseg);
                vl = *(const uint4*)(al + (size_t)gmf * F + kk0 + fseg);
            }
            *(uint4*)&sAhi[frow][fseg] = vh;
            *(uint4*)&sAlo[frow][fseg] = vl;
            *(uint4*)&sBhi[frow][fseg] =
                *(const uint4*)(g_wt_hi + wtoff + (size_t)frow * KTOT + kkw + fseg);
            *(uint4*)&sBlo[frow][fseg] =
                *(const uint4*)(g_wt_lo + wtoff + (size_t)frow * KTOT + kkw + fseg);
        }
        __syncthreads();

#pragma unroll
        for (int ks = 0; ks < 2; ks++) {
            uint32_t ahf[2][4], alf[2][4], bhf[4][2], blf[4][2];
#pragma unroll
            for (int mi = 0; mi < 2; mi++) {
                ldm_x4(ahf[mi], sm32(&sAhi[mb + mi * 16 + a_r][ks * 16 + a_c]));
                ldm_x4(alf[mi], sm32(&sAlo[mb + mi * 16 + a_r][ks * 16 + a_c]));
            }
#pragma unroll
            for (int ni = 0; ni < 4; ni++) {
                ldm_x2(bhf[ni], sm32(&sBhi[nb + ni * 8 + b_r][ks * 16 + b_c]));
                ldm_x2(blf[ni], sm32(&sBlo[nb + ni * 8 + b_r][ks * 16 + b_c]));
            }
#pragma unroll
            for (int mi = 0; mi < 2; mi++)
#pragma unroll
                for (int ni = 0; ni < 4; ni++) {
                    mma16816(acc[mi][ni], ahf[mi], bhf[ni]);
                    mma16816(acc[mi][ni], ahf[mi], blf[ni]);
                    mma16816(acc[mi][ni], alf[mi], bhf[ni]);
                }
        }
        __syncthreads();
    }

    const int trow = lane >> 2;
    const int tcol = (lane & 3) * 2;
#pragma unroll
    for (int mi = 0; mi < 2; mi++) {
#pragma unroll
        for (int half = 0; half < 2; half++) {
            int m = m0 + mb + mi * 16 + trow + half * 8;
            if (m >= M) continue;
#pragma unroll
            for (int ni = 0; ni < 4; ni++) {
                int col = nb + ni * 8 + tcol;
                float vx = acc[mi][ni][half * 2 + 0];
                float vy = acc[mi][ni][half * 2 + 1];
                if (MODE <= 1) { vx += bias[col]; vy += bias[col + 1]; }
                if (MODE == 0) { vx = fmaxf(vx, 0.f); vy = fmaxf(vy, 0.f); }
                if (MODE == 0) {
                    __half2 f = __floats2half2_rn(vx, vy);
                    *(__half2*)(g_h1h16 + (size_t)m * F + col) = f;
                    unsigned hi, lo;
                    split2(vx, vy, hi, lo);
                    *(unsigned*)(g_h1hi + (size_t)m * F + col) = hi;
                    *(unsigned*)(g_h1lo + (size_t)m * F + col) = lo;
                } else if (MODE == 1) {
                    unsigned hi, lo;
                    split2(vx, vy, hi, lo);
                    *(unsigned*)(g_h2hi + (size_t)m * F + col) = hi;
                    *(unsigned*)(g_h2lo + (size_t)m * F + col) = lo;
                } else {
                    __half2 h = __floats2half2_rn(vx, vy);
                    *(__half2*)(g_ABh + (size_t)m * 256 + blockIdx.y * 128 + col) = h;
                }
            }
        }
    }
}

// ---------------- edge classifier: warp per edge (fp16 AB table) -----------------
__global__ __launch_bounds__(256)
void edge_kernel(const void* __restrict__ eidx,
                 const float* __restrict__ ea,
                 const float* __restrict__ Wc1,
                 const float* __restrict__ bc1,
                 const float* __restrict__ Wc2,
                 const float* __restrict__ bc2,
                 float* __restrict__ out)
{
    __shared__ float sWe0[128], sWe1[128], sWe2[128], sb[128], sw2[128];
    int tid = threadIdx.x;
    if (tid < 128) {
        sWe0[tid] = Wc1[256 * 128 + tid];
        sWe1[tid] = Wc1[257 * 128 + tid];
        sWe2[tid] = Wc1[258 * 128 + tid];
        sb[tid]   = bc1[tid];
        sw2[tid]  = Wc2[tid];
    }
    __syncthreads();

    int e = blockIdx.x * (blockDim.x >> 5) + (tid >> 5);
    if (e >= NE) return;
    int lane = tid & 31;
    int j = lane * 4;

    int s = load_idx(eidx, e);
    int d = load_idx(eidx, (long long)NE + e);

    uint2 av = *(const uint2*)(g_ABh + (size_t)s * 256 + j);
    uint2 bv = *(const uint2*)(g_ABh + (size_t)d * 256 + 128 + j);
    float2 a01 = __half22float2(*(__half2*)&av.x);
    float2 a23 = __half22float2(*(__half2*)&av.y);
    float2 b01 = __half22float2(*(__half2*)&bv.x);
    float2 b23 = __half22float2(*(__half2*)&bv.y);

    float4 w0 = *(const float4*)&sWe0[j];
    float4 w1 = *(const float4*)&sWe1[j];
    float4 w2 = *(const float4*)&sWe2[j];
    float4 bb = *(const float4*)&sb[j];
    float4 wc = *(const float4*)&sw2[j];

    float e0 = ea[(size_t)e * 3 + 0];
    float e1 = ea[(size_t)e * 3 + 1];
    float e2 = ea[(size_t)e * 3 + 2];

    float h, acc = 0.f;
    h = a01.x + b01.x + e0 * w0.x + e1 * w1.x + e2 * w2.x + bb.x;
    acc += fmaxf(h, 0.f) * wc.x;
    h = a01.y + b01.y + e0 * w0.y + e1 * w1.y + e2 * w2.y + bb.y;
    acc += fmaxf(h, 0.f) * wc.y;
    h = a23.x + b23.x + e0 * w0.z + e1 * w1.z + e2 * w2.z + bb.z;
    acc += fmaxf(h, 0.f) * wc.z;
    h = a23.y + b23.y + e0 * w0.w + e1 * w1.w + e2 * w2.w + bb.w;
    acc += fmaxf(h, 0.f) * wc.w;

#pragma unroll
    for (int off = 16; off > 0; off >>= 1)
        acc += __shfl_xor_sync(0xFFFFFFFFu, acc, off);

    if (lane == 0) out[e] = acc + bc2[0];
}

// ---------------- launch -----------------------------------------------------------
extern "C" void kernel_launch(void* const* d_in, const int* in_sizes, int n_in,
                              void* d_out, int out_size)
{
    const float* x    = (const float*)d_in[0];
    const void*  eidx = d_in[1];
    const float* ea   = (const float*)d_in[2];
    const float* W1l  = (const float*)d_in[3];
    const float* b1l  = (const float*)d_in[4];
    const float* W1r  = (const float*)d_in[5];
    const float* W2l  = (const float*)d_in[6];
    const float* b2l  = (const float*)d_in[7];
    const float* W2r  = (const float*)d_in[8];
    const float* Wc1  = (const float*)d_in[9];
    const float* bc1  = (const float*)d_in[10];
    const float* Wc2  = (const float*)d_in[11];
    const float* bc2  = (const float*)d_in[12];
    float* out = (float*)d_out;

    const int SCAN_BLOCKS = (NN + 1023) / 1024;  // 49

    long long setup_threads = (long long)NN + 98304 + (long long)NN * 32;
    int setup_grid = (int)((setup_threads + 255) / 256);
    setup_kernel<<<setup_grid, 256>>>(eidx, x, W1l, W1r, W2l, W2r, Wc1);

    hist_kernel<<<(NE + 255) / 256, 256>>>(eidx);
    scanA_kernel<<<SCAN_BLOCKS, 1024>>>();
    scanB_kernel<<<1, 64>>>(SCAN_BLOCKS);
    scanC_kernel<<<SCAN_BLOCKS, 1024>>>();
    scatter_kernel<<<(NE + 255) / 256, 256>>>(eidx);

    const int aggGrid  = (NN * 32 + 255) / 256;
    const int gemmGrid = (NN + 127) / 128;       // 391

    aggregate_kernel<0><<<aggGrid, 256>>>();
    mma_gemm<0><<<gemmGrid, 512>>>(b1l, NN);

    aggregate_kernel<1><<<aggGrid, 256>>>();
    mma_gemm<1><<<gemmGrid, 512>>>(b2l, NN);

    mma_gemm<2><<<dim3(gemmGrid, 2), 512>>>(nullptr, NN);

    edge_kernel<<<(NE * 32 + 255) / 256, 256>>>(eidx, ea, Wc1, bc1, Wc2, bc2, out);
}